// round 8
// baseline (speedup 1.0000x reference)
#include <cuda_runtime.h>
#include <stdint.h>

// Problem shapes (fixed by the dataset)
#define MQ   1024
#define NDB  4096
#define FD   128
#define TT   64
#define TPOSE 64
#define PPOSE 96
#define POSE_ROW (TPOSE*PPOSE)      // 6144
#define OUT_GATHER (MQ*POSE_ROW)    // 6291456

#define NSPLIT 32       // n-splits (128 n per block)
#define MBLK 128        // m per score block
#define NBLK 128        // n per score block
#define KCH  64         // k chunk

// Scratch (device globals — no allocation allowed)
__device__ float g_qt[FD*MQ];          // q transposed: [f][m]
__device__ float g_sumA[NDB];          // ||a_n||^2
__device__ float g_candVal[MQ*NSPLIT];
__device__ int   g_candIdx[MQ*NSPLIT];

// ---------------------------------------------------------------------------
// packed f32x2 helpers
// ---------------------------------------------------------------------------
__device__ __forceinline__ unsigned long long fma2(unsigned long long a,
                                                   unsigned long long b,
                                                   unsigned long long c) {
    unsigned long long d;
    asm("fma.rn.f32x2 %0, %1, %2, %3;" : "=l"(d) : "l"(a), "l"(b), "l"(c));
    return d;
}
__device__ __forceinline__ float2 unpack2(unsigned long long v) {
    float2 r;
    asm("mov.b64 {%0, %1}, %2;" : "=f"(r.x), "=f"(r.y) : "l"(v));
    return r;
}
__device__ __forceinline__ float4 add4(float4 a, float4 b) {
    return make_float4(a.x+b.x, a.y+b.y, a.z+b.z, a.w+b.w);
}

// ---------------------------------------------------------------------------
// Kernel A (fused): blocks [0,128) -> qmean; blocks [128,144) -> sumsq.
// qmean: thread = (ml, f4); 8 LDG.128 forced live per group (MLP=8) so the
// ~577-cyc DRAM latency is covered: 32768 thr x 8 x 16B ~ 4.2 MB in flight.
// ---------------------------------------------------------------------------
__global__ void pre_kernel(const float* __restrict__ x,
                           const float* __restrict__ audio) {
    int tid = threadIdx.x;
    if (blockIdx.x < 128) {
        __shared__ float sq[FD*9];    // [f][ml], stride 9
        int m0 = blockIdx.x * 8;
        int f4 = tid & 31;            // 0..31 (float4 group)
        int ml = tid >> 5;            // 0..7
        const float4* px = (const float4*)(x + (size_t)(m0 + ml) * TT * FD) + f4;
        float4 a0 = make_float4(0.f,0.f,0.f,0.f), a1 = a0;
        #pragma unroll
        for (int g = 0; g < TT; g += 8) {
            // 8 independent LDG.128 issued before any consumer
            float4 v0 = px[(g+0)*32];
            float4 v1 = px[(g+1)*32];
            float4 v2 = px[(g+2)*32];
            float4 v3 = px[(g+3)*32];
            float4 v4 = px[(g+4)*32];
            float4 v5 = px[(g+5)*32];
            float4 v6 = px[(g+6)*32];
            float4 v7 = px[(g+7)*32];
            a0 = add4(a0, add4(add4(v0, v1), add4(v2, v3)));
            a1 = add4(a1, add4(add4(v4, v5), add4(v6, v7)));
        }
        float4 s = add4(a0, a1);
        s.x *= (1.0f/64.0f); s.y *= (1.0f/64.0f);
        s.z *= (1.0f/64.0f); s.w *= (1.0f/64.0f);
        sq[(f4*4+0)*9 + ml] = s.x;
        sq[(f4*4+1)*9 + ml] = s.y;
        sq[(f4*4+2)*9 + ml] = s.z;
        sq[(f4*4+3)*9 + ml] = s.w;
        __syncthreads();
        for (int pos = tid; pos < 8*FD; pos += 256) {
            int f = pos >> 3, mj = pos & 7;
            g_qt[f*MQ + m0 + mj] = sq[f*9 + mj];
        }
    } else {
        int nb = (blockIdx.x - 128) * 256;
        int warp = tid >> 5, lane = tid & 31;
        for (int r = warp; r < 256; r += 8) {
            int n = nb + r;
            float4 v = *(const float4*)&audio[(size_t)n * FD + lane * 4];
            float s = v.x*v.x + v.y*v.y + v.z*v.z + v.w*v.w;
            #pragma unroll
            for (int off = 16; off > 0; off >>= 1)
                s += __shfl_down_sync(0xffffffffu, s, off);
            if (lane == 0) g_sumA[n] = s;
        }
    }
}

// ---------------------------------------------------------------------------
// Kernel B: fused score + partial argmin.  (unchanged from R7)
// Grid (NSPLIT=32, MQ/MBLK=8) = 256 CTAs (one wave at 2 CTAs/SM), 256 thr.
// Block tile 128 m x 128 n; thread tile 8 m x 8 n (n in f32x2 pairs).
// Smem 96.5 KB: Qd[64][256] (q duplicated pairs) + As[64][128] swizzled + Ss.
// score(n,m) = ||a_n||^2 - 2 a_n.q_m
// ---------------------------------------------------------------------------
__global__ void __launch_bounds__(256, 2) score_kernel(const float* __restrict__ audio) {
    extern __shared__ float smem[];
    float* Qd = smem;                       // 16384 floats [kl][2m] (dup pairs)
    float* As = smem + 16384;               // 8192 floats  [kl][n^swz]
    float* Ss = smem + 16384 + 8192;        // 128 floats

    int tid = threadIdx.x;
    int tn = tid & 15;        // 16 threads over n
    int tm = tid >> 4;        // 16 groups over m (8 m each)
    int m_base = blockIdx.y * MBLK;
    int nb     = blockIdx.x * NBLK;
    int c0 = tn * 4;

    unsigned long long acc[8][4];
    #pragma unroll
    for (int a = 0; a < 8; ++a)
        #pragma unroll
        for (int b = 0; b < 4; ++b) acc[a][b] = 0ull;

    #pragma unroll 1
    for (int ch = 0; ch < FD/KCH; ++ch) {
        int kbase = ch * KCH;
        __syncthreads();   // protect smem from prior-chunk readers

        // As[kl][n ^ swz]: transpose-load audio (8 LDG.128/thread).
        for (int i = tid; i < NBLK*16; i += 256) {
            int k4 = i & 15, n = i >> 4;
            float4 v = *(const float4*)&audio[(size_t)(nb + n) * FD + kbase + k4 * 4];
            int col = n ^ ((k4 & 7) << 2);
            int r = (k4 * 4) * NBLK + col;
            As[r]       = v.x;
            As[r + 128] = v.y;
            As[r + 256] = v.z;
            As[r + 384] = v.w;
        }
        // Qd fill: 8 LDG.128/thread from g_qt (coalesced), duplicated pairs
        // built in regs, stored as 2x STS.128.
        for (int i = tid; i < KCH*MBLK/4; i += 256) {
            int kl = i >> 5, mq = i & 31;     // 32 float4-of-m per k row
            float4 v = ((const float4*)(g_qt + (size_t)(kbase + kl) * MQ + m_base))[mq];
            float* dst = Qd + kl*256 + mq*8;
            *(float4*)(dst)     = make_float4(v.x, v.x, v.y, v.y);
            *(float4*)(dst + 4) = make_float4(v.z, v.z, v.w, v.w);
        }
        if (ch == 0 && tid < NBLK) Ss[tid] = g_sumA[nb + tid];
        __syncthreads();

        #pragma unroll 4
        for (int kl = 0; kl < KCH; ++kl) {
            int swz = ((kl >> 2) & 7) << 2;
            const float* rowA = As + kl * NBLK;
            int p0 = c0 ^ swz;
            ulonglong2 A0 = *(const ulonglong2*)(rowA + p0);        // n = c0..c0+3
            ulonglong2 A1 = *(const ulonglong2*)(rowA + p0 + 64);   // n = 64+c0..
            const ulonglong2* qrow = (const ulonglong2*)(Qd + kl*256 + tm*16);
            ulonglong2 Q0 = qrow[0], Q1 = qrow[1], Q2 = qrow[2], Q3 = qrow[3];
            acc[0][0] = fma2(A0.x, Q0.x, acc[0][0]);
            acc[0][1] = fma2(A0.y, Q0.x, acc[0][1]);
            acc[0][2] = fma2(A1.x, Q0.x, acc[0][2]);
            acc[0][3] = fma2(A1.y, Q0.x, acc[0][3]);
            acc[1][0] = fma2(A0.x, Q0.y, acc[1][0]);
            acc[1][1] = fma2(A0.y, Q0.y, acc[1][1]);
            acc[1][2] = fma2(A1.x, Q0.y, acc[1][2]);
            acc[1][3] = fma2(A1.y, Q0.y, acc[1][3]);
            acc[2][0] = fma2(A0.x, Q1.x, acc[2][0]);
            acc[2][1] = fma2(A0.y, Q1.x, acc[2][1]);
            acc[2][2] = fma2(A1.x, Q1.x, acc[2][2]);
            acc[2][3] = fma2(A1.y, Q1.x, acc[2][3]);
            acc[3][0] = fma2(A0.x, Q1.y, acc[3][0]);
            acc[3][1] = fma2(A0.y, Q1.y, acc[3][1]);
            acc[3][2] = fma2(A1.x, Q1.y, acc[3][2]);
            acc[3][3] = fma2(A1.y, Q1.y, acc[3][3]);
            acc[4][0] = fma2(A0.x, Q2.x, acc[4][0]);
            acc[4][1] = fma2(A0.y, Q2.x, acc[4][1]);
            acc[4][2] = fma2(A1.x, Q2.x, acc[4][2]);
            acc[4][3] = fma2(A1.y, Q2.x, acc[4][3]);
            acc[5][0] = fma2(A0.x, Q2.y, acc[5][0]);
            acc[5][1] = fma2(A0.y, Q2.y, acc[5][1]);
            acc[5][2] = fma2(A1.x, Q2.y, acc[5][2]);
            acc[5][3] = fma2(A1.y, Q2.y, acc[5][3]);
            acc[6][0] = fma2(A0.x, Q3.x, acc[6][0]);
            acc[6][1] = fma2(A0.y, Q3.x, acc[6][1]);
            acc[6][2] = fma2(A1.x, Q3.x, acc[6][2]);
            acc[6][3] = fma2(A1.y, Q3.x, acc[6][3]);
            acc[7][0] = fma2(A0.x, Q3.y, acc[7][0]);
            acc[7][1] = fma2(A0.y, Q3.y, acc[7][1]);
            acc[7][2] = fma2(A1.x, Q3.y, acc[7][2]);
            acc[7][3] = fma2(A1.y, Q3.y, acc[7][3]);
        }
    }

    // Epilogue: score = sumA - 2*dot; per-thread argmin over 8 n, then
    // shfl-reduce across the 16 tn-lanes (ties -> lower n, matching argmin).
    #pragma unroll
    for (int mi = 0; mi < 8; ++mi) {
        float bv = 3.4e38f; int bi = 0;
        #pragma unroll
        for (int pj = 0; pj < 4; ++pj) {
            float2 d = unpack2(acc[mi][pj]);
            int nloc = (pj < 2) ? (c0 + pj * 2) : (64 + c0 + (pj - 2) * 2);
            float s0 = Ss[nloc]     - 2.0f * d.x;
            float s1 = Ss[nloc + 1] - 2.0f * d.y;
            if (s0 < bv) { bv = s0; bi = nb + nloc; }
            if (s1 < bv) { bv = s1; bi = nb + nloc + 1; }
        }
        float v = bv; int ix = bi;
        #pragma unroll
        for (int off = 8; off > 0; off >>= 1) {
            float ov = __shfl_down_sync(0xffffffffu, v, off, 16);
            int   oi = __shfl_down_sync(0xffffffffu, ix, off, 16);
            if (ov < v || (ov == v && oi < ix)) { v = ov; ix = oi; }
        }
        if (tn == 0) {
            int m = m_base + tm * 8 + mi;
            g_candVal[m * NSPLIT + blockIdx.x] = v;
            g_candIdx[m * NSPLIT + blockIdx.x] = ix;
        }
    }
}

// ---------------------------------------------------------------------------
// Kernel C: final argmin (warp-parallel over 32 splits) + pose row gather.
// ---------------------------------------------------------------------------
__global__ void gather_kernel(const float* __restrict__ pose,
                              const float* __restrict__ dummy,
                              float* __restrict__ out,
                              int extra, int dn) {
    int m = blockIdx.x;
    __shared__ int s_idx;
    if (threadIdx.x < 32) {
        int lane = threadIdx.x;
        float v = g_candVal[m * NSPLIT + lane];
        int  ix = g_candIdx[m * NSPLIT + lane];
        #pragma unroll
        for (int off = 16; off > 0; off >>= 1) {
            float ov = __shfl_down_sync(0xffffffffu, v, off);
            int   oi = __shfl_down_sync(0xffffffffu, ix, off);
            if (ov < v || (ov == v && oi < ix)) { v = ov; ix = oi; }
        }
        if (lane == 0) s_idx = ix;
    }
    __syncthreads();
    int idx = s_idx;
    const float4* src = (const float4*)&pose[(size_t)idx * POSE_ROW];
    float4*       dst = (float4*)&out[(size_t)m * POSE_ROW];
    float4 r0 = src[threadIdx.x];
    float4 r1 = src[threadIdx.x + 256];
    float4 r2 = src[threadIdx.x + 512];
    float4 r3 = src[threadIdx.x + 768];
    float4 r4 = src[threadIdx.x + 1024];
    float4 r5 = src[threadIdx.x + 1280];
    dst[threadIdx.x]        = r0;
    dst[threadIdx.x + 256]  = r1;
    dst[threadIdx.x + 512]  = r2;
    dst[threadIdx.x + 768]  = r3;
    dst[threadIdx.x + 1024] = r4;
    dst[threadIdx.x + 1280] = r5;

    if (m == 0 && threadIdx.x == 0 && extra > 0) {
        float l = 0.f;
        for (int i = 0; i < dn; ++i) l += dummy[i];
        for (int e = 0; e < extra; ++e) out[OUT_GATHER + e] = l;
    }
}

// ---------------------------------------------------------------------------
// Launch. Inputs: [0]=x (M,T,F), [1]=y, [2]=audio (N,F), [3]=pose (N,Tp,P),
// [4]=dummy. Output: pose gather (M,Tp,P).
// ---------------------------------------------------------------------------
extern "C" void kernel_launch(void* const* d_in, const int* in_sizes, int n_in,
                              void* d_out, int out_size) {
    const float* x     = (const float*)d_in[0];
    const float* audio = (const float*)d_in[2];
    const float* pose  = (const float*)d_in[3];
    const float* dummy = (const float*)d_in[4];
    float* out = (float*)d_out;

    const int smemC = (16384 + 8192 + 128) * (int)sizeof(float);  // 98816 B
    cudaFuncSetAttribute(score_kernel,
                         cudaFuncAttributeMaxDynamicSharedMemorySize, smemC);

    pre_kernel<<<144, 256>>>(x, audio);
    score_kernel<<<dim3(NSPLIT, MQ / MBLK), 256, smemC>>>(audio);

    int extra = out_size - OUT_GATHER;
    int dn = (n_in > 4) ? in_sizes[4] : 1;
    gather_kernel<<<MQ, 256>>>(pose, dummy, out, extra, dn);
}

// round 9
// speedup vs baseline: 1.0042x; 1.0042x over previous
#include <cuda_runtime.h>
#include <stdint.h>

// Problem shapes (fixed by the dataset)
#define MQ   1024
#define NDB  4096
#define FD   128
#define TT   64
#define TPOSE 64
#define PPOSE 96
#define POSE_ROW (TPOSE*PPOSE)      // 6144
#define OUT_GATHER (MQ*POSE_ROW)    // 6291456

#define NSPLIT 32       // n-splits (128 n per block)
#define MBLK 128        // m per score block
#define NBLK 128        // n per score block
#define KCH  64         // k chunk

// Scratch (device globals — no allocation allowed)
__device__ float g_qt[FD*MQ];          // q transposed: [f][m]
__device__ float g_sumA[NDB];          // ||a_n||^2
__device__ float g_candVal[MQ*NSPLIT];
__device__ int   g_candIdx[MQ*NSPLIT];

// ---------------------------------------------------------------------------
// packed f32x2 helpers
// ---------------------------------------------------------------------------
__device__ __forceinline__ unsigned long long fma2(unsigned long long a,
                                                   unsigned long long b,
                                                   unsigned long long c) {
    unsigned long long d;
    asm("fma.rn.f32x2 %0, %1, %2, %3;" : "=l"(d) : "l"(a), "l"(b), "l"(c));
    return d;
}
__device__ __forceinline__ float2 unpack2(unsigned long long v) {
    float2 r;
    asm("mov.b64 {%0, %1}, %2;" : "=f"(r.x), "=f"(r.y) : "l"(v));
    return r;
}
__device__ __forceinline__ float4 add4(float4 a, float4 b) {
    return make_float4(a.x+b.x, a.y+b.y, a.z+b.z, a.w+b.w);
}

// ---------------------------------------------------------------------------
// Kernel A (fused): blocks [0,128) -> qmean; blocks [128,144) -> sumsq.
// qmean: thread = (ml, f4); 8 LDG.128 forced live per group (MLP=8) so the
// ~577-cyc DRAM latency is covered: 32768 thr x 8 x 16B ~ 4.2 MB in flight.
// ---------------------------------------------------------------------------
__global__ void pre_kernel(const float* __restrict__ x,
                           const float* __restrict__ audio) {
    int tid = threadIdx.x;
    if (blockIdx.x < 128) {
        __shared__ float sq[FD*9];    // [f][ml], stride 9
        int m0 = blockIdx.x * 8;
        int f4 = tid & 31;            // 0..31 (float4 group)
        int ml = tid >> 5;            // 0..7
        const float4* px = (const float4*)(x + (size_t)(m0 + ml) * TT * FD) + f4;
        float4 a0 = make_float4(0.f,0.f,0.f,0.f), a1 = a0;
        #pragma unroll
        for (int g = 0; g < TT; g += 8) {
            // 8 independent LDG.128 issued before any consumer
            float4 v0 = px[(g+0)*32];
            float4 v1 = px[(g+1)*32];
            float4 v2 = px[(g+2)*32];
            float4 v3 = px[(g+3)*32];
            float4 v4 = px[(g+4)*32];
            float4 v5 = px[(g+5)*32];
            float4 v6 = px[(g+6)*32];
            float4 v7 = px[(g+7)*32];
            a0 = add4(a0, add4(add4(v0, v1), add4(v2, v3)));
            a1 = add4(a1, add4(add4(v4, v5), add4(v6, v7)));
        }
        float4 s = add4(a0, a1);
        s.x *= (1.0f/64.0f); s.y *= (1.0f/64.0f);
        s.z *= (1.0f/64.0f); s.w *= (1.0f/64.0f);
        sq[(f4*4+0)*9 + ml] = s.x;
        sq[(f4*4+1)*9 + ml] = s.y;
        sq[(f4*4+2)*9 + ml] = s.z;
        sq[(f4*4+3)*9 + ml] = s.w;
        __syncthreads();
        for (int pos = tid; pos < 8*FD; pos += 256) {
            int f = pos >> 3, mj = pos & 7;
            g_qt[f*MQ + m0 + mj] = sq[f*9 + mj];
        }
    } else {
        int nb = (blockIdx.x - 128) * 256;
        int warp = tid >> 5, lane = tid & 31;
        for (int r = warp; r < 256; r += 8) {
            int n = nb + r;
            float4 v = *(const float4*)&audio[(size_t)n * FD + lane * 4];
            float s = v.x*v.x + v.y*v.y + v.z*v.z + v.w*v.w;
            #pragma unroll
            for (int off = 16; off > 0; off >>= 1)
                s += __shfl_down_sync(0xffffffffu, s, off);
            if (lane == 0) g_sumA[n] = s;
        }
    }
}

// ---------------------------------------------------------------------------
// Kernel B: fused score + partial argmin.  (unchanged from R7)
// Grid (NSPLIT=32, MQ/MBLK=8) = 256 CTAs (one wave at 2 CTAs/SM), 256 thr.
// Block tile 128 m x 128 n; thread tile 8 m x 8 n (n in f32x2 pairs).
// Smem 96.5 KB: Qd[64][256] (q duplicated pairs) + As[64][128] swizzled + Ss.
// score(n,m) = ||a_n||^2 - 2 a_n.q_m
// ---------------------------------------------------------------------------
__global__ void __launch_bounds__(256, 2) score_kernel(const float* __restrict__ audio) {
    extern __shared__ float smem[];
    float* Qd = smem;                       // 16384 floats [kl][2m] (dup pairs)
    float* As = smem + 16384;               // 8192 floats  [kl][n^swz]
    float* Ss = smem + 16384 + 8192;        // 128 floats

    int tid = threadIdx.x;
    int tn = tid & 15;        // 16 threads over n
    int tm = tid >> 4;        // 16 groups over m (8 m each)
    int m_base = blockIdx.y * MBLK;
    int nb     = blockIdx.x * NBLK;
    int c0 = tn * 4;

    unsigned long long acc[8][4];
    #pragma unroll
    for (int a = 0; a < 8; ++a)
        #pragma unroll
        for (int b = 0; b < 4; ++b) acc[a][b] = 0ull;

    #pragma unroll 1
    for (int ch = 0; ch < FD/KCH; ++ch) {
        int kbase = ch * KCH;
        __syncthreads();   // protect smem from prior-chunk readers

        // As[kl][n ^ swz]: transpose-load audio (8 LDG.128/thread).
        for (int i = tid; i < NBLK*16; i += 256) {
            int k4 = i & 15, n = i >> 4;
            float4 v = *(const float4*)&audio[(size_t)(nb + n) * FD + kbase + k4 * 4];
            int col = n ^ ((k4 & 7) << 2);
            int r = (k4 * 4) * NBLK + col;
            As[r]       = v.x;
            As[r + 128] = v.y;
            As[r + 256] = v.z;
            As[r + 384] = v.w;
        }
        // Qd fill: 8 LDG.128/thread from g_qt (coalesced), duplicated pairs
        // built in regs, stored as 2x STS.128.
        for (int i = tid; i < KCH*MBLK/4; i += 256) {
            int kl = i >> 5, mq = i & 31;     // 32 float4-of-m per k row
            float4 v = ((const float4*)(g_qt + (size_t)(kbase + kl) * MQ + m_base))[mq];
            float* dst = Qd + kl*256 + mq*8;
            *(float4*)(dst)     = make_float4(v.x, v.x, v.y, v.y);
            *(float4*)(dst + 4) = make_float4(v.z, v.z, v.w, v.w);
        }
        if (ch == 0 && tid < NBLK) Ss[tid] = g_sumA[nb + tid];
        __syncthreads();

        #pragma unroll 4
        for (int kl = 0; kl < KCH; ++kl) {
            int swz = ((kl >> 2) & 7) << 2;
            const float* rowA = As + kl * NBLK;
            int p0 = c0 ^ swz;
            ulonglong2 A0 = *(const ulonglong2*)(rowA + p0);        // n = c0..c0+3
            ulonglong2 A1 = *(const ulonglong2*)(rowA + p0 + 64);   // n = 64+c0..
            const ulonglong2* qrow = (const ulonglong2*)(Qd + kl*256 + tm*16);
            ulonglong2 Q0 = qrow[0], Q1 = qrow[1], Q2 = qrow[2], Q3 = qrow[3];
            acc[0][0] = fma2(A0.x, Q0.x, acc[0][0]);
            acc[0][1] = fma2(A0.y, Q0.x, acc[0][1]);
            acc[0][2] = fma2(A1.x, Q0.x, acc[0][2]);
            acc[0][3] = fma2(A1.y, Q0.x, acc[0][3]);
            acc[1][0] = fma2(A0.x, Q0.y, acc[1][0]);
            acc[1][1] = fma2(A0.y, Q0.y, acc[1][1]);
            acc[1][2] = fma2(A1.x, Q0.y, acc[1][2]);
            acc[1][3] = fma2(A1.y, Q0.y, acc[1][3]);
            acc[2][0] = fma2(A0.x, Q1.x, acc[2][0]);
            acc[2][1] = fma2(A0.y, Q1.x, acc[2][1]);
            acc[2][2] = fma2(A1.x, Q1.x, acc[2][2]);
            acc[2][3] = fma2(A1.y, Q1.x, acc[2][3]);
            acc[3][0] = fma2(A0.x, Q1.y, acc[3][0]);
            acc[3][1] = fma2(A0.y, Q1.y, acc[3][1]);
            acc[3][2] = fma2(A1.x, Q1.y, acc[3][2]);
            acc[3][3] = fma2(A1.y, Q1.y, acc[3][3]);
            acc[4][0] = fma2(A0.x, Q2.x, acc[4][0]);
            acc[4][1] = fma2(A0.y, Q2.x, acc[4][1]);
            acc[4][2] = fma2(A1.x, Q2.x, acc[4][2]);
            acc[4][3] = fma2(A1.y, Q2.x, acc[4][3]);
            acc[5][0] = fma2(A0.x, Q2.y, acc[5][0]);
            acc[5][1] = fma2(A0.y, Q2.y, acc[5][1]);
            acc[5][2] = fma2(A1.x, Q2.y, acc[5][2]);
            acc[5][3] = fma2(A1.y, Q2.y, acc[5][3]);
            acc[6][0] = fma2(A0.x, Q3.x, acc[6][0]);
            acc[6][1] = fma2(A0.y, Q3.x, acc[6][1]);
            acc[6][2] = fma2(A1.x, Q3.x, acc[6][2]);
            acc[6][3] = fma2(A1.y, Q3.x, acc[6][3]);
            acc[7][0] = fma2(A0.x, Q3.y, acc[7][0]);
            acc[7][1] = fma2(A0.y, Q3.y, acc[7][1]);
            acc[7][2] = fma2(A1.x, Q3.y, acc[7][2]);
            acc[7][3] = fma2(A1.y, Q3.y, acc[7][3]);
        }
    }

    // Epilogue: score = sumA - 2*dot; per-thread argmin over 8 n, then
    // shfl-reduce across the 16 tn-lanes (ties -> lower n, matching argmin).
    #pragma unroll
    for (int mi = 0; mi < 8; ++mi) {
        float bv = 3.4e38f; int bi = 0;
        #pragma unroll
        for (int pj = 0; pj < 4; ++pj) {
            float2 d = unpack2(acc[mi][pj]);
            int nloc = (pj < 2) ? (c0 + pj * 2) : (64 + c0 + (pj - 2) * 2);
            float s0 = Ss[nloc]     - 2.0f * d.x;
            float s1 = Ss[nloc + 1] - 2.0f * d.y;
            if (s0 < bv) { bv = s0; bi = nb + nloc; }
            if (s1 < bv) { bv = s1; bi = nb + nloc + 1; }
        }
        float v = bv; int ix = bi;
        #pragma unroll
        for (int off = 8; off > 0; off >>= 1) {
            float ov = __shfl_down_sync(0xffffffffu, v, off, 16);
            int   oi = __shfl_down_sync(0xffffffffu, ix, off, 16);
            if (ov < v || (ov == v && oi < ix)) { v = ov; ix = oi; }
        }
        if (tn == 0) {
            int m = m_base + tm * 8 + mi;
            g_candVal[m * NSPLIT + blockIdx.x] = v;
            g_candIdx[m * NSPLIT + blockIdx.x] = ix;
        }
    }
}

// ---------------------------------------------------------------------------
// Kernel C: final argmin (warp-parallel over 32 splits) + pose row gather.
// ---------------------------------------------------------------------------
__global__ void gather_kernel(const float* __restrict__ pose,
                              const float* __restrict__ dummy,
                              float* __restrict__ out,
                              int extra, int dn) {
    int m = blockIdx.x;
    __shared__ int s_idx;
    if (threadIdx.x < 32) {
        int lane = threadIdx.x;
        float v = g_candVal[m * NSPLIT + lane];
        int  ix = g_candIdx[m * NSPLIT + lane];
        #pragma unroll
        for (int off = 16; off > 0; off >>= 1) {
            float ov = __shfl_down_sync(0xffffffffu, v, off);
            int   oi = __shfl_down_sync(0xffffffffu, ix, off);
            if (ov < v || (ov == v && oi < ix)) { v = ov; ix = oi; }
        }
        if (lane == 0) s_idx = ix;
    }
    __syncthreads();
    int idx = s_idx;
    const float4* src = (const float4*)&pose[(size_t)idx * POSE_ROW];
    float4*       dst = (float4*)&out[(size_t)m * POSE_ROW];
    float4 r0 = src[threadIdx.x];
    float4 r1 = src[threadIdx.x + 256];
    float4 r2 = src[threadIdx.x + 512];
    float4 r3 = src[threadIdx.x + 768];
    float4 r4 = src[threadIdx.x + 1024];
    float4 r5 = src[threadIdx.x + 1280];
    dst[threadIdx.x]        = r0;
    dst[threadIdx.x + 256]  = r1;
    dst[threadIdx.x + 512]  = r2;
    dst[threadIdx.x + 768]  = r3;
    dst[threadIdx.x + 1024] = r4;
    dst[threadIdx.x + 1280] = r5;

    if (m == 0 && threadIdx.x == 0 && extra > 0) {
        float l = 0.f;
        for (int i = 0; i < dn; ++i) l += dummy[i];
        for (int e = 0; e < extra; ++e) out[OUT_GATHER + e] = l;
    }
}

// ---------------------------------------------------------------------------
// Launch. Inputs: [0]=x (M,T,F), [1]=y, [2]=audio (N,F), [3]=pose (N,Tp,P),
// [4]=dummy. Output: pose gather (M,Tp,P).
// ---------------------------------------------------------------------------
extern "C" void kernel_launch(void* const* d_in, const int* in_sizes, int n_in,
                              void* d_out, int out_size) {
    const float* x     = (const float*)d_in[0];
    const float* audio = (const float*)d_in[2];
    const float* pose  = (const float*)d_in[3];
    const float* dummy = (const float*)d_in[4];
    float* out = (float*)d_out;

    const int smemC = (16384 + 8192 + 128) * (int)sizeof(float);  // 98816 B
    cudaFuncSetAttribute(score_kernel,
                         cudaFuncAttributeMaxDynamicSharedMemorySize, smemC);

    pre_kernel<<<144, 256>>>(x, audio);
    score_kernel<<<dim3(NSPLIT, MQ / MBLK), 256, smemC>>>(audio);

    int extra = out_size - OUT_GATHER;
    int dn = (n_in > 4) ? in_sizes[4] : 1;
    gather_kernel<<<MQ, 256>>>(pose, dummy, out, extra, dn);
}